// round 8
// baseline (speedup 1.0000x reference)
#include <cuda_runtime.h>
#include <cuda_fp16.h>
#include <cstdint>

#define D     128
#define HID   256
#define KIN   384
#define TM    128
#define NTHR  512
#define MAXN  50000

// -------------------- device scratch --------------------
__device__ float g_sent_agg[MAXN * D];
__device__ float g_recv_agg[MAXN * D];
__device__ __align__(16) __half g_ew1t[HID * KIN];   // W1^T [256,384] fp16
__device__ __align__(16) __half g_ew2t[D * HID];     // W2^T [128,256]
__device__ __align__(16) __half g_nw1t[HID * KIN];
__device__ __align__(16) __half g_nw2t[D * HID];

__device__ __forceinline__ void mma16(float d[4], const uint32_t a[4], const uint32_t b[2]) {
    asm volatile("mma.sync.aligned.m16n8k16.row.col.f32.f16.f16.f32 "
                 "{%0,%1,%2,%3}, {%4,%5,%6,%7}, {%8,%9}, {%0,%1,%2,%3};"
                 : "+f"(d[0]), "+f"(d[1]), "+f"(d[2]), "+f"(d[3])
                 : "r"(a[0]), "r"(a[1]), "r"(a[2]), "r"(a[3]),
                   "r"(b[0]), "r"(b[1]));
}

__device__ __forceinline__ void red_add_v4(float* p, float4 v) {
    asm volatile("red.global.add.v4.f32 [%0], {%1,%2,%3,%4};"
                 :: "l"(p), "f"(v.x), "f"(v.y), "f"(v.z), "f"(v.w) : "memory");
}

__device__ __forceinline__ void cp16(__half* smem_dst, const __half* gsrc) {
    uint32_t s = (uint32_t)__cvta_generic_to_shared(smem_dst);
    asm volatile("cp.async.cg.shared.global [%0], [%1], 16;" :: "r"(s), "l"(gsrc));
}
#define CP_COMMIT() asm volatile("cp.async.commit_group;" ::: "memory")
#define CP_WAIT0()  asm volatile("cp.async.wait_group 0;"  ::: "memory")

// -------------------- weight prep: transpose + fp16 --------------------
__global__ void prep_weights(const float* __restrict__ eW1, const float* __restrict__ eW2,
                             const float* __restrict__ nW1, const float* __restrict__ nW2)
{
    int idx0 = blockIdx.x * blockDim.x + threadIdx.x;
    int stride = gridDim.x * blockDim.x;
    for (int i = idx0; i < HID * KIN; i += stride) {
        int n = i / KIN, k = i - n * KIN;
        g_ew1t[i] = __float2half_rn(eW1[k * HID + n]);
        g_nw1t[i] = __float2half_rn(nW1[k * HID + n]);
    }
    for (int i = idx0; i < D * HID; i += stride) {
        int n = i / HID, k = i - n * HID;
        g_ew2t[i] = __float2half_rn(eW2[k * D + n]);
        g_nw2t[i] = __float2half_rn(nW2[k * D + n]);
    }
}

// -------------------- smem layout --------------------
// half offsets: As0/As1 [128][40], Bs0/Bs1 [256][40], Hs [128][264] (aliases),
// Bs2 x2 [128][40] after Hs.  float region: Hs2 [128][132] aliases Hs.
#define HAS0   0
#define HAS1   5120
#define HBS0   10240
#define HBS1   20480
#define HHS    0
#define HS_STRIDE_H 264
#define HBS2_0 33792
#define HBS2_1 38912
// float offsets
#define OFF_HS2   0
#define HS2_STRIDE 132
#define OFF_B1S   22016
#define OFF_B2S   22272
#define OFF_SID   22400
#define OFF_RID   22528
#define SMEM_BYTES 90624

// -------------------- fused MLP kernel --------------------
// mode 0: edge MLP (+ fused segment-sum), mode 1: node MLP
__global__ __launch_bounds__(NTHR, 1)
void gn_mlp_kernel(const float* __restrict__ in0,
                   const float* __restrict__ edge_feat,
                   const int*   __restrict__ senders,
                   const int*   __restrict__ receivers,
                   const float* __restrict__ b1,
                   const float* __restrict__ b2,
                   float* __restrict__ out,
                   int M_total, int mode)
{
    extern __shared__ float sm[];
    __half* hsm = (__half*)sm;
    float* b1s = sm + OFF_B1S;
    float* b2s = sm + OFF_B2S;
    int*   sid = (int*)(sm + OFF_SID);
    int*   rid = (int*)(sm + OFF_RID);

    const int tid  = threadIdx.x;
    const int lane = tid & 31;
    const int w    = tid >> 5;
    const int g    = lane >> 2;        // group 0..7
    const int t    = lane & 3;         // thread-in-group 0..3
    const int mw   = w & 3;            // M tile (32 rows)
    const int nw   = w >> 2;           // N tile
    const int m0   = blockIdx.x * TM;

    const __half* __restrict__ w1t = (mode == 0) ? g_ew1t : g_nw1t;
    const __half* __restrict__ w2t = (mode == 0) ? g_ew2t : g_nw2t;

    for (int i = tid; i < HID; i += NTHR) b1s[i] = b1[i];
    for (int i = tid; i < D;   i += NTHR) b2s[i] = b2[i];
    if (mode == 0) {
        for (int i = tid; i < TM; i += NTHR) {
            int e = m0 + i;
            sid[i] = (e < M_total) ? senders[e]   : 0;
            rid[i] = (e < M_total) ? receivers[e] : 0;
        }
    }
    __syncthreads();

    // ---- per-thread A-gather geometry: 2 float4 segments (tid, tid+512) ----
    int a_row[2], a_sc[2];
    const float* a_p0[2]; const float* a_p1[2]; const float* a_p2[2];
    bool a_ok[2];
    #pragma unroll
    for (int i = 0; i < 2; ++i) {
        int seg = tid + NTHR * i;
        a_row[i] = seg >> 3; a_sc[i] = seg & 7;
        int m = m0 + a_row[i];
        a_ok[i] = (m < M_total);
        int mm = a_ok[i] ? m : 0;
        if (mode == 0) {
            a_p0[i] = edge_feat + (size_t)mm * D;
            a_p1[i] = in0 + (size_t)sid[a_row[i]] * D;
            a_p2[i] = in0 + (size_t)rid[a_row[i]] * D;
        } else {
            a_p0[i] = in0 + (size_t)mm * D;
            a_p1[i] = g_sent_agg + (size_t)mm * D;
            a_p2[i] = g_recv_agg + (size_t)mm * D;
        }
    }

    float4 a_pre[2];
    auto ldA = [&](int c) {
        int co = (c & 3) * 32;
        #pragma unroll
        for (int i = 0; i < 2; ++i) {
            const float* base = (c < 4) ? a_p0[i] : (c < 8) ? a_p1[i] : a_p2[i];
            a_pre[i] = a_ok[i] ? *(const float4*)(base + co + a_sc[i] * 4)
                               : make_float4(0.f, 0.f, 0.f, 0.f);
        }
    };
    auto stA = [&](__half* dst) {
        #pragma unroll
        for (int i = 0; i < 2; ++i) {
            __half2 lo = __floats2half2_rn(a_pre[i].x, a_pre[i].y);
            __half2 hi = __floats2half2_rn(a_pre[i].z, a_pre[i].w);
            uint2 tv;
            tv.x = *(uint32_t*)&lo; tv.y = *(uint32_t*)&hi;
            *(uint2*)(dst + a_row[i] * 40 + a_sc[i] * 4) = tv;
        }
    };
    auto cpB1 = [&](int c, __half* dst) {           // 256 rows x 4 segs of 8 halves
        #pragma unroll
        for (int seg = tid, it = 0; it < 2; seg += NTHR, ++it) {
            int row = seg >> 2, sc = seg & 3;
            cp16(dst + row * 40 + sc * 8, w1t + (size_t)row * KIN + c * 32 + sc * 8);
        }
    };
    auto cpB2 = [&](int c, __half* dst) {           // 128 rows x 4 segs
        int row = tid >> 2, sc = tid & 3;
        cp16(dst + row * 40 + sc * 8, w2t + (size_t)row * HID + c * 32 + sc * 8);
    };

    // ============ stage 1: [128,384] @ W1^T -> [128,256]; warp tile 32x64 ============
    float acc[2][8][4];
    {
        const int n0 = nw * 64;
        #pragma unroll
        for (int mi = 0; mi < 2; ++mi)
            #pragma unroll
            for (int ni = 0; ni < 8; ++ni) {
                float bv0 = b1s[n0 + ni * 8 + 2 * t];
                float bv1 = b1s[n0 + ni * 8 + 2 * t + 1];
                acc[mi][ni][0] = bv0; acc[mi][ni][1] = bv1;
                acc[mi][ni][2] = bv0; acc[mi][ni][3] = bv1;
            }
    }

    ldA(0);
    cpB1(0, hsm + HBS0);
    CP_COMMIT();
    stA(hsm + HAS0);
    CP_WAIT0();
    __syncthreads();

    #pragma unroll 1
    for (int c = 0; c < 12; ++c) {
        if (c < 11) {
            ldA(c + 1);
            cpB1(c + 1, hsm + ((c + 1) & 1 ? HBS1 : HBS0));
            CP_COMMIT();
        }
        const __half* Ab = hsm + ((c & 1) ? HAS1 : HAS0);
        const __half* Bb = hsm + ((c & 1) ? HBS1 : HBS0);
        #pragma unroll
        for (int kk = 0; kk < 2; ++kk) {
            const int kh = kk * 16 + 2 * t;
            uint32_t af[2][4], bf[8][2];
            #pragma unroll
            for (int mi = 0; mi < 2; ++mi) {
                int r = mw * 32 + mi * 16;
                af[mi][0] = *(const uint32_t*)(Ab + (r + g) * 40 + kh);
                af[mi][1] = *(const uint32_t*)(Ab + (r + 8 + g) * 40 + kh);
                af[mi][2] = *(const uint32_t*)(Ab + (r + g) * 40 + kh + 8);
                af[mi][3] = *(const uint32_t*)(Ab + (r + 8 + g) * 40 + kh + 8);
            }
            #pragma unroll
            for (int ni = 0; ni < 8; ++ni) {
                int n = nw * 64 + ni * 8;
                bf[ni][0] = *(const uint32_t*)(Bb + (n + g) * 40 + kh);
                bf[ni][1] = *(const uint32_t*)(Bb + (n + g) * 40 + kh + 8);
            }
            #pragma unroll
            for (int mi = 0; mi < 2; ++mi)
                #pragma unroll
                for (int ni = 0; ni < 8; ++ni)
                    mma16(acc[mi][ni], af[mi], bf[ni]);
        }
        if (c < 11) {
            stA(hsm + ((c + 1) & 1 ? HAS1 : HAS0));
            CP_WAIT0();
        }
        __syncthreads();
    }

    // ============ hidden: relu -> fp16, store to Hs (aliases As/Bs) ============
    {
        __half* Hs = hsm + HHS;
        #pragma unroll
        for (int mi = 0; mi < 2; ++mi) {
            int r = mw * 32 + mi * 16;
            #pragma unroll
            for (int ni = 0; ni < 8; ++ni) {
                int n = nw * 64 + ni * 8 + 2 * t;
                __half2 v0 = __floats2half2_rn(fmaxf(acc[mi][ni][0], 0.f), fmaxf(acc[mi][ni][1], 0.f));
                __half2 v1 = __floats2half2_rn(fmaxf(acc[mi][ni][2], 0.f), fmaxf(acc[mi][ni][3], 0.f));
                *(uint32_t*)(Hs + (r + g) * HS_STRIDE_H + n)     = *(uint32_t*)&v0;
                *(uint32_t*)(Hs + (r + 8 + g) * HS_STRIDE_H + n) = *(uint32_t*)&v1;
            }
        }
    }
    __syncthreads();

    // ============ stage 2: H[128,256] @ W2^T -> [128,128]; warp tile 32x32 ============
    float acc2[2][4][4];
    {
        const int n0 = nw * 32;
        #pragma unroll
        for (int mi = 0; mi < 2; ++mi)
            #pragma unroll
            for (int ni = 0; ni < 4; ++ni) {
                float bv0 = b2s[n0 + ni * 8 + 2 * t];
                float bv1 = b2s[n0 + ni * 8 + 2 * t + 1];
                acc2[mi][ni][0] = bv0; acc2[mi][ni][1] = bv1;
                acc2[mi][ni][2] = bv0; acc2[mi][ni][3] = bv1;
            }
    }

    cpB2(0, hsm + HBS2_0);
    CP_COMMIT();
    CP_WAIT0();
    __syncthreads();

    const __half* Hs = hsm + HHS;
    #pragma unroll 1
    for (int c = 0; c < 8; ++c) {
        if (c < 7) {
            cpB2(c + 1, hsm + ((c + 1) & 1 ? HBS2_1 : HBS2_0));
            CP_COMMIT();
        }
        const __half* Bb = hsm + ((c & 1) ? HBS2_1 : HBS2_0);
        #pragma unroll
        for (int kk = 0; kk < 2; ++kk) {
            const int kh = kk * 16 + 2 * t;
            const int kg = c * 32 + kh;
            uint32_t af[2][4], bf[4][2];
            #pragma unroll
            for (int mi = 0; mi < 2; ++mi) {
                int r = mw * 32 + mi * 16;
                af[mi][0] = *(const uint32_t*)(Hs + (r + g) * HS_STRIDE_H + kg);
                af[mi][1] = *(const uint32_t*)(Hs + (r + 8 + g) * HS_STRIDE_H + kg);
                af[mi][2] = *(const uint32_t*)(Hs + (r + g) * HS_STRIDE_H + kg + 8);
                af[mi][3] = *(const uint32_t*)(Hs + (r + 8 + g) * HS_STRIDE_H + kg + 8);
            }
            #pragma unroll
            for (int ni = 0; ni < 4; ++ni) {
                int n = nw * 32 + ni * 8;
                bf[ni][0] = *(const uint32_t*)(Bb + (n + g) * 40 + kh);
                bf[ni][1] = *(const uint32_t*)(Bb + (n + g) * 40 + kh + 8);
            }
            #pragma unroll
            for (int mi = 0; mi < 2; ++mi)
                #pragma unroll
                for (int ni = 0; ni < 4; ++ni)
                    mma16(acc2[mi][ni], af[mi], bf[ni]);
        }
        if (c < 7) CP_WAIT0();
        __syncthreads();
    }

    // ============ frags -> Hs2 fp32 (aliases Hs; stage2 reads done) ============
    {
        float* Hs2 = sm + OFF_HS2;
        #pragma unroll
        for (int mi = 0; mi < 2; ++mi) {
            int r = mw * 32 + mi * 16;
            #pragma unroll
            for (int ni = 0; ni < 4; ++ni) {
                int n = nw * 32 + ni * 8 + 2 * t;
                Hs2[(r + g) * HS2_STRIDE + n]     = acc2[mi][ni][0];
                Hs2[(r + g) * HS2_STRIDE + n + 1] = acc2[mi][ni][1];
                Hs2[(r + 8 + g) * HS2_STRIDE + n]     = acc2[mi][ni][2];
                Hs2[(r + 8 + g) * HS2_STRIDE + n + 1] = acc2[mi][ni][3];
            }
        }
    }
    __syncthreads();

    // ============ epilogue: contiguous v4 stores + fused segment-sum ============
    {
        const float* Hs2 = sm + OFF_HS2;
        int r = tid >> 2;
        int q = tid & 3;
        int m = m0 + r;
        if (m < M_total) {
            float* op = out + (size_t)m * D + q * 32;
            const float* hp = Hs2 + r * HS2_STRIDE + q * 32;
            if (mode == 0) {
                float* ps = g_sent_agg + (size_t)sid[r] * D + q * 32;
                float* pr = g_recv_agg + (size_t)rid[r] * D + q * 32;
                #pragma unroll
                for (int i = 0; i < 8; ++i) {
                    float4 v = *(const float4*)(hp + 4 * i);
                    *(float4*)(op + 4 * i) = v;
                    red_add_v4(ps + 4 * i, v);
                    red_add_v4(pr + 4 * i, v);
                }
            } else {
                #pragma unroll
                for (int i = 0; i < 8; ++i)
                    *(float4*)(op + 4 * i) = *(const float4*)(hp + 4 * i);
            }
        }
    }
}

// -------------------- launch --------------------
extern "C" void kernel_launch(void* const* d_in, const int* in_sizes, int n_in,
                              void* d_out, int out_size)
{
    const float* node_feat = (const float*)d_in[0];
    const float* edge_feat = (const float*)d_in[1];
    const int*   senders   = (const int*)  d_in[2];
    const int*   receivers = (const int*)  d_in[3];
    const float* eW1 = (const float*)d_in[4];
    const float* eb1 = (const float*)d_in[5];
    const float* eW2 = (const float*)d_in[6];
    const float* eb2 = (const float*)d_in[7];
    const float* nW1 = (const float*)d_in[8];
    const float* nb1 = (const float*)d_in[9];
    const float* nW2 = (const float*)d_in[10];
    const float* nb2 = (const float*)d_in[11];

    const int N = in_sizes[0] / D;
    const int E = in_sizes[2];

    float* new_nodes = (float*)d_out;
    float* new_edges = new_nodes + (size_t)N * D;

    cudaFuncSetAttribute(gn_mlp_kernel,
                         cudaFuncAttributeMaxDynamicSharedMemorySize, SMEM_BYTES);

    void *pa, *pb;
    cudaGetSymbolAddress(&pa, g_sent_agg);
    cudaGetSymbolAddress(&pb, g_recv_agg);
    cudaMemsetAsync(pa, 0, sizeof(float) * MAXN * D);
    cudaMemsetAsync(pb, 0, sizeof(float) * MAXN * D);

    prep_weights<<<192, 512>>>(eW1, eW2, nW1, nW2);

    int eblocks = (E + TM - 1) / TM;
    gn_mlp_kernel<<<eblocks, NTHR, SMEM_BYTES>>>(
        node_feat, edge_feat, senders, receivers,
        eb1, eb2, new_edges, E, 0);

    int nblocks = (N + TM - 1) / TM;
    gn_mlp_kernel<<<nblocks, NTHR, SMEM_BYTES>>>(
        node_feat, nullptr, nullptr, nullptr,
        nb1, nb2, new_nodes, N, 1);
}

// round 9
// speedup vs baseline: 1.5359x; 1.5359x over previous
#include <cuda_runtime.h>
#include <cuda_fp16.h>
#include <cstdint>

#define D     128
#define HID   256
#define KIN   384
#define TM    128
#define NTHR  512
#define MAXN  50000

// -------------------- device scratch --------------------
__device__ float g_sent_agg[MAXN * D];
__device__ float g_recv_agg[MAXN * D];
__device__ __align__(16) __half g_ew1t[HID * KIN];   // W1^T [256,384] fp16
__device__ __align__(16) __half g_ew2t[D * HID];     // W2^T [128,256]
__device__ __align__(16) __half g_nw1t[HID * KIN];
__device__ __align__(16) __half g_nw2t[D * HID];

__device__ __forceinline__ void mma16(float d[4], const uint32_t a[4], const uint32_t b[2]) {
    asm volatile("mma.sync.aligned.m16n8k16.row.col.f32.f16.f16.f32 "
                 "{%0,%1,%2,%3}, {%4,%5,%6,%7}, {%8,%9}, {%0,%1,%2,%3};"
                 : "+f"(d[0]), "+f"(d[1]), "+f"(d[2]), "+f"(d[3])
                 : "r"(a[0]), "r"(a[1]), "r"(a[2]), "r"(a[3]),
                   "r"(b[0]), "r"(b[1]));
}

__device__ __forceinline__ void red_add_v4(float* p, float4 v) {
    asm volatile("red.global.add.v4.f32 [%0], {%1,%2,%3,%4};"
                 :: "l"(p), "f"(v.x), "f"(v.y), "f"(v.z), "f"(v.w) : "memory");
}

__device__ __forceinline__ void cp16(__half* smem_dst, const __half* gsrc) {
    uint32_t s = (uint32_t)__cvta_generic_to_shared(smem_dst);
    asm volatile("cp.async.cg.shared.global [%0], [%1], 16;" :: "r"(s), "l"(gsrc));
}
#define CP_COMMIT() asm volatile("cp.async.commit_group;" ::: "memory")
#define CP_WAIT0()  asm volatile("cp.async.wait_group 0;"  ::: "memory")

// -------------------- weight prep: transpose + fp16 --------------------
__global__ void prep_weights(const float* __restrict__ eW1, const float* __restrict__ eW2,
                             const float* __restrict__ nW1, const float* __restrict__ nW2)
{
    int idx0 = blockIdx.x * blockDim.x + threadIdx.x;
    int stride = gridDim.x * blockDim.x;
    for (int i = idx0; i < HID * KIN; i += stride) {
        int n = i / KIN, k = i - n * KIN;
        g_ew1t[i] = __float2half_rn(eW1[k * HID + n]);
        g_nw1t[i] = __float2half_rn(nW1[k * HID + n]);
    }
    for (int i = idx0; i < D * HID; i += stride) {
        int n = i / HID, k = i - n * HID;
        g_ew2t[i] = __float2half_rn(eW2[k * D + n]);
        g_nw2t[i] = __float2half_rn(nW2[k * D + n]);
    }
}

// -------------------- smem layout --------------------
// half offsets: As0/As1 [128][40], Bs0/Bs1 [256][40], Hs [128][264] (aliases),
// Bs2 x2 [128][40] after Hs.  float region: Hs2 [128][132] aliases Hs.
#define HAS0   0
#define HAS1   5120
#define HBS0   10240
#define HBS1   20480
#define HHS    0
#define HS_STRIDE_H 264
#define HBS2_0 33792
#define HBS2_1 38912
// float offsets
#define OFF_HS2   0
#define HS2_STRIDE 132
#define OFF_B1S   22016
#define OFF_B2S   22272
#define OFF_SID   22400
#define OFF_RID   22528
#define SMEM_BYTES 90624

// -------------------- fused MLP kernel --------------------
// mode 0: edge MLP (+ fused segment-sum), mode 1: node MLP
__global__ __launch_bounds__(NTHR, 1)
void gn_mlp_kernel(const float* __restrict__ in0,
                   const float* __restrict__ edge_feat,
                   const int*   __restrict__ senders,
                   const int*   __restrict__ receivers,
                   const float* __restrict__ b1,
                   const float* __restrict__ b2,
                   float* __restrict__ out,
                   int M_total, int mode)
{
    extern __shared__ float sm[];
    __half* hsm = (__half*)sm;
    float* b1s = sm + OFF_B1S;
    float* b2s = sm + OFF_B2S;
    int*   sid = (int*)(sm + OFF_SID);
    int*   rid = (int*)(sm + OFF_RID);

    const int tid  = threadIdx.x;
    const int lane = tid & 31;
    const int w    = tid >> 5;
    const int g    = lane >> 2;        // group 0..7
    const int t    = lane & 3;         // thread-in-group 0..3
    const int mw   = w & 3;            // M tile (32 rows)
    const int nw   = w >> 2;           // N tile
    const int m0   = blockIdx.x * TM;

    const __half* __restrict__ w1t = (mode == 0) ? g_ew1t : g_nw1t;
    const __half* __restrict__ w2t = (mode == 0) ? g_ew2t : g_nw2t;

    for (int i = tid; i < HID; i += NTHR) b1s[i] = b1[i];
    for (int i = tid; i < D;   i += NTHR) b2s[i] = b2[i];
    if (mode == 0) {
        for (int i = tid; i < TM; i += NTHR) {
            int e = m0 + i;
            sid[i] = (e < M_total) ? senders[e]   : 0;
            rid[i] = (e < M_total) ? receivers[e] : 0;
        }
    }
    __syncthreads();

    // ---- per-thread A-gather geometry: 2 float4 segments (tid, tid+512) ----
    int a_row[2], a_sc[2];
    const float* a_p0[2]; const float* a_p1[2]; const float* a_p2[2];
    bool a_ok[2];
    #pragma unroll
    for (int i = 0; i < 2; ++i) {
        int seg = tid + NTHR * i;
        a_row[i] = seg >> 3; a_sc[i] = seg & 7;
        int m = m0 + a_row[i];
        a_ok[i] = (m < M_total);
        int mm = a_ok[i] ? m : 0;
        if (mode == 0) {
            a_p0[i] = edge_feat + (size_t)mm * D;
            a_p1[i] = in0 + (size_t)sid[a_row[i]] * D;
            a_p2[i] = in0 + (size_t)rid[a_row[i]] * D;
        } else {
            a_p0[i] = in0 + (size_t)mm * D;
            a_p1[i] = g_sent_agg + (size_t)mm * D;
            a_p2[i] = g_recv_agg + (size_t)mm * D;
        }
    }

    float4 a_pre[2];
    auto ldA = [&](int c) {
        int co = (c & 3) * 32;
        #pragma unroll
        for (int i = 0; i < 2; ++i) {
            const float* base = (c < 4) ? a_p0[i] : (c < 8) ? a_p1[i] : a_p2[i];
            a_pre[i] = a_ok[i] ? *(const float4*)(base + co + a_sc[i] * 4)
                               : make_float4(0.f, 0.f, 0.f, 0.f);
        }
    };
    auto stA = [&](__half* dst) {
        #pragma unroll
        for (int i = 0; i < 2; ++i) {
            __half2 lo = __floats2half2_rn(a_pre[i].x, a_pre[i].y);
            __half2 hi = __floats2half2_rn(a_pre[i].z, a_pre[i].w);
            uint2 tv;
            tv.x = *(uint32_t*)&lo; tv.y = *(uint32_t*)&hi;
            *(uint2*)(dst + a_row[i] * 40 + a_sc[i] * 4) = tv;
        }
    };
    auto cpB1 = [&](int c, __half* dst) {           // 256 rows x 4 segs of 8 halves
        #pragma unroll
        for (int seg = tid, it = 0; it < 2; seg += NTHR, ++it) {
            int row = seg >> 2, sc = seg & 3;
            cp16(dst + row * 40 + sc * 8, w1t + (size_t)row * KIN + c * 32 + sc * 8);
        }
    };
    auto cpB2 = [&](int c, __half* dst) {           // 128 rows x 4 segs
        int row = tid >> 2, sc = tid & 3;
        cp16(dst + row * 40 + sc * 8, w2t + (size_t)row * HID + c * 32 + sc * 8);
    };

    // ============ stage 1: [128,384] @ W1^T -> [128,256]; warp tile 32x64 ============
    float acc[2][8][4];
    {
        const int n0 = nw * 64;
        #pragma unroll
        for (int mi = 0; mi < 2; ++mi)
            #pragma unroll
            for (int ni = 0; ni < 8; ++ni) {
                float bv0 = b1s[n0 + ni * 8 + 2 * t];
                float bv1 = b1s[n0 + ni * 8 + 2 * t + 1];
                acc[mi][ni][0] = bv0; acc[mi][ni][1] = bv1;
                acc[mi][ni][2] = bv0; acc[mi][ni][3] = bv1;
            }
    }

    ldA(0);
    cpB1(0, hsm + HBS0);
    CP_COMMIT();
    stA(hsm + HAS0);
    CP_WAIT0();
    __syncthreads();

    #pragma unroll 1
    for (int c = 0; c < 12; ++c) {
        if (c < 11) {
            ldA(c + 1);
            cpB1(c + 1, hsm + ((c + 1) & 1 ? HBS1 : HBS0));
            CP_COMMIT();
        }
        const __half* Ab = hsm + ((c & 1) ? HAS1 : HAS0);
        const __half* Bb = hsm + ((c & 1) ? HBS1 : HBS0);
        #pragma unroll
        for (int kk = 0; kk < 2; ++kk) {
            const int kh = kk * 16 + 2 * t;
            uint32_t af[2][4], bf[8][2];
            #pragma unroll
            for (int mi = 0; mi < 2; ++mi) {
                int r = mw * 32 + mi * 16;
                af[mi][0] = *(const uint32_t*)(Ab + (r + g) * 40 + kh);
                af[mi][1] = *(const uint32_t*)(Ab + (r + 8 + g) * 40 + kh);
                af[mi][2] = *(const uint32_t*)(Ab + (r + g) * 40 + kh + 8);
                af[mi][3] = *(const uint32_t*)(Ab + (r + 8 + g) * 40 + kh + 8);
            }
            #pragma unroll
            for (int ni = 0; ni < 8; ++ni) {
                int n = nw * 64 + ni * 8;
                bf[ni][0] = *(const uint32_t*)(Bb + (n + g) * 40 + kh);
                bf[ni][1] = *(const uint32_t*)(Bb + (n + g) * 40 + kh + 8);
            }
            #pragma unroll
            for (int mi = 0; mi < 2; ++mi)
                #pragma unroll
                for (int ni = 0; ni < 8; ++ni)
                    mma16(acc[mi][ni], af[mi], bf[ni]);
        }
        if (c < 11) {
            stA(hsm + ((c + 1) & 1 ? HAS1 : HAS0));
            CP_WAIT0();
        }
        __syncthreads();
    }

    // ============ hidden: relu -> fp16, store to Hs (aliases As/Bs) ============
    {
        __half* Hs = hsm + HHS;
        #pragma unroll
        for (int mi = 0; mi < 2; ++mi) {
            int r = mw * 32 + mi * 16;
            #pragma unroll
            for (int ni = 0; ni < 8; ++ni) {
                int n = nw * 64 + ni * 8 + 2 * t;
                __half2 v0 = __floats2half2_rn(fmaxf(acc[mi][ni][0], 0.f), fmaxf(acc[mi][ni][1], 0.f));
                __half2 v1 = __floats2half2_rn(fmaxf(acc[mi][ni][2], 0.f), fmaxf(acc[mi][ni][3], 0.f));
                *(uint32_t*)(Hs + (r + g) * HS_STRIDE_H + n)     = *(uint32_t*)&v0;
                *(uint32_t*)(Hs + (r + 8 + g) * HS_STRIDE_H + n) = *(uint32_t*)&v1;
            }
        }
    }
    __syncthreads();

    // ============ stage 2: H[128,256] @ W2^T -> [128,128]; warp tile 32x32 ============
    float acc2[2][4][4];
    {
        const int n0 = nw * 32;
        #pragma unroll
        for (int mi = 0; mi < 2; ++mi)
            #pragma unroll
            for (int ni = 0; ni < 4; ++ni) {
                float bv0 = b2s[n0 + ni * 8 + 2 * t];
                float bv1 = b2s[n0 + ni * 8 + 2 * t + 1];
                acc2[mi][ni][0] = bv0; acc2[mi][ni][1] = bv1;
                acc2[mi][ni][2] = bv0; acc2[mi][ni][3] = bv1;
            }
    }

    cpB2(0, hsm + HBS2_0);
    CP_COMMIT();
    CP_WAIT0();
    __syncthreads();

    const __half* Hs = hsm + HHS;
    #pragma unroll 1
    for (int c = 0; c < 8; ++c) {
        if (c < 7) {
            cpB2(c + 1, hsm + ((c + 1) & 1 ? HBS2_1 : HBS2_0));
            CP_COMMIT();
        }
        const __half* Bb = hsm + ((c & 1) ? HBS2_1 : HBS2_0);
        #pragma unroll
        for (int kk = 0; kk < 2; ++kk) {
            const int kh = kk * 16 + 2 * t;
            const int kg = c * 32 + kh;
            uint32_t af[2][4], bf[4][2];
            #pragma unroll
            for (int mi = 0; mi < 2; ++mi) {
                int r = mw * 32 + mi * 16;
                af[mi][0] = *(const uint32_t*)(Hs + (r + g) * HS_STRIDE_H + kg);
                af[mi][1] = *(const uint32_t*)(Hs + (r + 8 + g) * HS_STRIDE_H + kg);
                af[mi][2] = *(const uint32_t*)(Hs + (r + g) * HS_STRIDE_H + kg + 8);
                af[mi][3] = *(const uint32_t*)(Hs + (r + 8 + g) * HS_STRIDE_H + kg + 8);
            }
            #pragma unroll
            for (int ni = 0; ni < 4; ++ni) {
                int n = nw * 32 + ni * 8;
                bf[ni][0] = *(const uint32_t*)(Bb + (n + g) * 40 + kh);
                bf[ni][1] = *(const uint32_t*)(Bb + (n + g) * 40 + kh + 8);
            }
            #pragma unroll
            for (int mi = 0; mi < 2; ++mi)
                #pragma unroll
                for (int ni = 0; ni < 4; ++ni)
                    mma16(acc2[mi][ni], af[mi], bf[ni]);
        }
        if (c < 7) CP_WAIT0();
        __syncthreads();
    }

    // ============ frags -> Hs2 fp32 (aliases Hs; stage2 reads done) ============
    {
        float* Hs2 = sm + OFF_HS2;
        #pragma unroll
        for (int mi = 0; mi < 2; ++mi) {
            int r = mw * 32 + mi * 16;
            #pragma unroll
            for (int ni = 0; ni < 4; ++ni) {
                int n = nw * 32 + ni * 8 + 2 * t;
                Hs2[(r + g) * HS2_STRIDE + n]     = acc2[mi][ni][0];
                Hs2[(r + g) * HS2_STRIDE + n + 1] = acc2[mi][ni][1];
                Hs2[(r + 8 + g) * HS2_STRIDE + n]     = acc2[mi][ni][2];
                Hs2[(r + 8 + g) * HS2_STRIDE + n + 1] = acc2[mi][ni][3];
            }
        }
    }
    __syncthreads();

    // ============ epilogue: contiguous v4 stores + fused segment-sum ============
    {
        const float* Hs2 = sm + OFF_HS2;
        int r = tid >> 2;
        int q = tid & 3;
        int m = m0 + r;
        if (m < M_total) {
            float* op = out + (size_t)m * D + q * 32;
            const float* hp = Hs2 + r * HS2_STRIDE + q * 32;
            if (mode == 0) {
                float* ps = g_sent_agg + (size_t)sid[r] * D + q * 32;
                float* pr = g_recv_agg + (size_t)rid[r] * D + q * 32;
                #pragma unroll
                for (int i = 0; i < 8; ++i) {
                    float4 v = *(const float4*)(hp + 4 * i);
                    *(float4*)(op + 4 * i) = v;
                    red_add_v4(ps + 4 * i, v);
                    red_add_v4(pr + 4 * i, v);
                }
            } else {
                #pragma unroll
                for (int i = 0; i < 8; ++i)
                    *(float4*)(op + 4 * i) = *(const float4*)(hp + 4 * i);
            }
        }
    }
}

// -------------------- launch --------------------
extern "C" void kernel_launch(void* const* d_in, const int* in_sizes, int n_in,
                              void* d_out, int out_size)
{
    const float* node_feat = (const float*)d_in[0];
    const float* edge_feat = (const float*)d_in[1];
    const int*   senders   = (const int*)  d_in[2];
    const int*   receivers = (const int*)  d_in[3];
    const float* eW1 = (const float*)d_in[4];
    const float* eb1 = (const float*)d_in[5];
    const float* eW2 = (const float*)d_in[6];
    const float* eb2 = (const float*)d_in[7];
    const float* nW1 = (const float*)d_in[8];
    const float* nb1 = (const float*)d_in[9];
    const float* nW2 = (const float*)d_in[10];
    const float* nb2 = (const float*)d_in[11];

    const int N = in_sizes[0] / D;
    const int E = in_sizes[2];

    float* new_nodes = (float*)d_out;
    float* new_edges = new_nodes + (size_t)N * D;

    cudaFuncSetAttribute(gn_mlp_kernel,
                         cudaFuncAttributeMaxDynamicSharedMemorySize, SMEM_BYTES);

    void *pa, *pb;
    cudaGetSymbolAddress(&pa, g_sent_agg);
    cudaGetSymbolAddress(&pb, g_recv_agg);
    cudaMemsetAsync(pa, 0, sizeof(float) * MAXN * D);
    cudaMemsetAsync(pb, 0, sizeof(float) * MAXN * D);

    prep_weights<<<192, 512>>>(eW1, eW2, nW1, nW2);

    int eblocks = (E + TM - 1) / TM;
    gn_mlp_kernel<<<eblocks, NTHR, SMEM_BYTES>>>(
        node_feat, edge_feat, senders, receivers,
        eb1, eb2, new_edges, E, 0);

    int nblocks = (N + TM - 1) / TM;
    gn_mlp_kernel<<<nblocks, NTHR, SMEM_BYTES>>>(
        node_feat, nullptr, nullptr, nullptr,
        nb1, nb2, new_nodes, N, 1);
}

// round 10
// speedup vs baseline: 1.7024x; 1.1084x over previous
#include <cuda_runtime.h>
#include <cuda_fp16.h>
#include <cstdint>

#define D     128
#define HID   256
#define KIN   384
#define TM    128
#define NTHR  512
#define MAXN  50000

// -------------------- device scratch --------------------
__device__ float g_sent_agg[MAXN * D];
__device__ float g_recv_agg[MAXN * D];
__device__ __align__(16) __half g_ew1t[HID * KIN];   // W1^T [256,384] fp16
__device__ __align__(16) __half g_ew2t[D * HID];     // W2^T [128,256]
__device__ __align__(16) __half g_nw1t[HID * KIN];
__device__ __align__(16) __half g_nw2t[D * HID];

__device__ __forceinline__ void mma16(float d[4], const uint32_t a[4], const uint32_t b[2]) {
    asm volatile("mma.sync.aligned.m16n8k16.row.col.f32.f16.f16.f32 "
                 "{%0,%1,%2,%3}, {%4,%5,%6,%7}, {%8,%9}, {%0,%1,%2,%3};"
                 : "+f"(d[0]), "+f"(d[1]), "+f"(d[2]), "+f"(d[3])
                 : "r"(a[0]), "r"(a[1]), "r"(a[2]), "r"(a[3]),
                   "r"(b[0]), "r"(b[1]));
}

__device__ __forceinline__ void ldm_x4(uint32_t r[4], uint32_t saddr) {
    asm volatile("ldmatrix.sync.aligned.m8n8.x4.shared.b16 {%0,%1,%2,%3}, [%4];"
                 : "=r"(r[0]), "=r"(r[1]), "=r"(r[2]), "=r"(r[3]) : "r"(saddr));
}

__device__ __forceinline__ void red_add_v4(float* p, float4 v) {
    asm volatile("red.global.add.v4.f32 [%0], {%1,%2,%3,%4};"
                 :: "l"(p), "f"(v.x), "f"(v.y), "f"(v.z), "f"(v.w) : "memory");
}

__device__ __forceinline__ void cp16(__half* smem_dst, const __half* gsrc) {
    uint32_t s = (uint32_t)__cvta_generic_to_shared(smem_dst);
    asm volatile("cp.async.cg.shared.global [%0], [%1], 16;" :: "r"(s), "l"(gsrc));
}
#define CP_COMMIT() asm volatile("cp.async.commit_group;" ::: "memory")
#define CP_WAIT0()  asm volatile("cp.async.wait_group 0;"  ::: "memory")

// -------------------- weight prep: transpose + fp16 --------------------
__global__ void prep_weights(const float* __restrict__ eW1, const float* __restrict__ eW2,
                             const float* __restrict__ nW1, const float* __restrict__ nW2)
{
    int idx0 = blockIdx.x * blockDim.x + threadIdx.x;
    int stride = gridDim.x * blockDim.x;
    for (int i = idx0; i < HID * KIN; i += stride) {
        int n = i / KIN, k = i - n * KIN;
        g_ew1t[i] = __float2half_rn(eW1[k * HID + n]);
        g_nw1t[i] = __float2half_rn(nW1[k * HID + n]);
    }
    for (int i = idx0; i < D * HID; i += stride) {
        int n = i / HID, k = i - n * HID;
        g_ew2t[i] = __float2half_rn(eW2[k * D + n]);
        g_nw2t[i] = __float2half_rn(nW2[k * D + n]);
    }
}

// -------------------- smem layout --------------------
// chunk = 64 k-cols, row stride 72 halves (144B, 16B-aligned, ldmatrix conflict-free)
// half offsets:
//   As0 [128][72] @0, As1 @9216, Bs0 [256][72] @18432, Bs1 @36864 (end 55296)
//   Hs  [128][264] @0 (aliases As/Bs, 33792 halves)
//   Bs2_0 [128][72] @33792, Bs2_1 @43008 (alias dead B1 region)
// float offsets:
//   Hs2 [128][132] @0 (bytes [0,67584) — exactly abuts Bs2_0 at byte 67584)
//   b1s @27648, b2s @27904, sid @28032, rid @28160
#define HAS0   0
#define HAS1   9216
#define HBS0   18432
#define HBS1   36864
#define HHS    0
#define HS_STRIDE_H 264
#define HBS2_0 33792
#define HBS2_1 43008
#define OFF_HS2   0
#define HS2_STRIDE 132
#define OFF_B1S   27648
#define OFF_B2S   27904
#define OFF_SID   28032
#define OFF_RID   28160
#define SMEM_BYTES 113152

// -------------------- fused MLP kernel --------------------
// mode 0: edge MLP (+ fused segment-sum), mode 1: node MLP
__global__ __launch_bounds__(NTHR, 1)
void gn_mlp_kernel(const float* __restrict__ in0,
                   const float* __restrict__ edge_feat,
                   const int*   __restrict__ senders,
                   const int*   __restrict__ receivers,
                   const float* __restrict__ b1,
                   const float* __restrict__ b2,
                   float* __restrict__ out,
                   int M_total, int mode)
{
    extern __shared__ float sm[];
    __half* hsm = (__half*)sm;
    float* b1s = sm + OFF_B1S;
    float* b2s = sm + OFF_B2S;
    int*   sid = (int*)(sm + OFF_SID);
    int*   rid = (int*)(sm + OFF_RID);

    const int tid  = threadIdx.x;
    const int lane = tid & 31;
    const int w    = tid >> 5;
    const int g    = lane >> 2;
    const int t    = lane & 3;
    const int mw   = w & 3;            // M tile (32 rows)
    const int nw   = w >> 2;           // N tile
    const int m0   = blockIdx.x * TM;

    const __half* __restrict__ w1t = (mode == 0) ? g_ew1t : g_nw1t;
    const __half* __restrict__ w2t = (mode == 0) ? g_ew2t : g_nw2t;

    const uint32_t smb = (uint32_t)__cvta_generic_to_shared(hsm);

    // ldmatrix lane geometry
    const int al_row = lane & 15;                      // A: row within 16x16 tile
    const uint32_t al_kb = (uint32_t)(lane >> 4) * 16; // A: k-half byte offset
    const int bl_j = lane >> 3, bl_i = lane & 7;       // B: matrix id / row
    const int b_row = ((bl_j >> 1) << 3) + bl_i;       // B: row within 16-n group
    const uint32_t b_kb = (uint32_t)(bl_j & 1) * 16;   // B: k-half byte offset

    for (int i = tid; i < HID; i += NTHR) b1s[i] = b1[i];
    for (int i = tid; i < D;   i += NTHR) b2s[i] = b2[i];
    if (mode == 0) {
        for (int i = tid; i < TM; i += NTHR) {
            int e = m0 + i;
            sid[i] = (e < M_total) ? senders[e]   : 0;
            rid[i] = (e < M_total) ? receivers[e] : 0;
        }
    }
    __syncthreads();

    // ---- A gather: 4 float4 segs/thread/chunk; rows arow+32i, col seg asc ----
    const int arow = tid >> 4;          // 0..31
    const int asc  = tid & 15;          // float4 index within 64 cols
    float4 a_pre[4];
    auto ldA = [&](int c) {
        const int csel = c >> 1;
        const int co = (c & 1) * 64 + asc * 4;
        #pragma unroll
        for (int i = 0; i < 4; ++i) {
            int r = arow + 32 * i;
            int m = m0 + r;
            bool ok = (m < M_total);
            const float* bp;
            if (mode == 0) {
                int s = (csel == 0) ? m : (csel == 1 ? sid[r] : rid[r]);
                bp = ((csel == 0) ? edge_feat : in0) + (size_t)s * D;
            } else {
                bp = ((csel == 0) ? in0 : (csel == 1 ? g_sent_agg : g_recv_agg)) + (size_t)m * D;
            }
            a_pre[i] = ok ? *(const float4*)(bp + co) : make_float4(0.f, 0.f, 0.f, 0.f);
        }
    };
    auto stA = [&](__half* dst) {
        #pragma unroll
        for (int i = 0; i < 4; ++i) {
            __half2 lo = __floats2half2_rn(a_pre[i].x, a_pre[i].y);
            __half2 hi = __floats2half2_rn(a_pre[i].z, a_pre[i].w);
            uint2 tv;
            tv.x = *(uint32_t*)&lo; tv.y = *(uint32_t*)&hi;
            *(uint2*)(dst + (arow + 32 * i) * 72 + asc * 4) = tv;
        }
    };
    auto cpB1 = [&](int c, __half* dst) {       // 256 rows x 64 halves = 2048 cp16
        #pragma unroll
        for (int it = 0; it < 4; ++it) {
            int seg = tid + NTHR * it;
            int row = seg >> 3, sc = seg & 7;
            cp16(dst + row * 72 + sc * 8, w1t + (size_t)row * KIN + c * 64 + sc * 8);
        }
    };
    auto cpB2 = [&](int c, __half* dst) {       // 128 rows x 64 halves = 1024 cp16
        #pragma unroll
        for (int it = 0; it < 2; ++it) {
            int seg = tid + NTHR * it;
            int row = seg >> 3, sc = seg & 7;
            cp16(dst + row * 72 + sc * 8, w2t + (size_t)row * HID + c * 64 + sc * 8);
        }
    };

    // ============ stage 1: [128,384] @ W1^T -> [128,256]; warp tile 32x64 ============
    float acc[2][8][4];
    {
        const int n0 = nw * 64;
        #pragma unroll
        for (int mi = 0; mi < 2; ++mi)
            #pragma unroll
            for (int ni = 0; ni < 8; ++ni) {
                float bv0 = b1s[n0 + ni * 8 + 2 * t];
                float bv1 = b1s[n0 + ni * 8 + 2 * t + 1];
                acc[mi][ni][0] = bv0; acc[mi][ni][1] = bv1;
                acc[mi][ni][2] = bv0; acc[mi][ni][3] = bv1;
            }
    }

    // per-warp ldmatrix lane base offsets (bytes), stage1 buffers
    const uint32_t a1_lane = (uint32_t)(mw * 32 + al_row) * 144 + al_kb;
    const uint32_t b1_lane = (uint32_t)(nw * 64 + b_row) * 144 + b_kb;

    ldA(0);
    cpB1(0, hsm + HBS0);
    CP_COMMIT();
    stA(hsm + HAS0);
    CP_WAIT0();
    __syncthreads();

    #pragma unroll 1
    for (int c = 0; c < 6; ++c) {
        if (c < 5) {
            ldA(c + 1);
            cpB1(c + 1, hsm + ((c + 1) & 1 ? HBS1 : HBS0));
            CP_COMMIT();
        }
        const uint32_t Ab = smb + ((c & 1) ? HAS1 : HAS0) * 2 + a1_lane;
        const uint32_t Bb = smb + ((c & 1) ? HBS1 : HBS0) * 2 + b1_lane;
        #pragma unroll
        for (int kk = 0; kk < 4; ++kk) {
            const uint32_t kb = (uint32_t)kk * 32;
            uint32_t af[2][4], bf[4][4];
            ldm_x4(af[0], Ab + kb);
            ldm_x4(af[1], Ab + 16 * 144 + kb);
            #pragma unroll
            for (int np = 0; np < 4; ++np)
                ldm_x4(bf[np], Bb + (uint32_t)np * (16 * 144) + kb);
            #pragma unroll
            for (int mi = 0; mi < 2; ++mi)
                #pragma unroll
                for (int np = 0; np < 4; ++np) {
                    mma16(acc[mi][2 * np],     af[mi], &bf[np][0]);
                    mma16(acc[mi][2 * np + 1], af[mi], &bf[np][2]);
                }
        }
        if (c < 5) {
            stA(hsm + ((c + 1) & 1 ? HAS1 : HAS0));
            CP_WAIT0();
        }
        __syncthreads();
    }

    // ============ hidden: relu -> fp16, store to Hs (aliases As/Bs) ============
    {
        __half* Hs = hsm + HHS;
        #pragma unroll
        for (int mi = 0; mi < 2; ++mi) {
            int r = mw * 32 + mi * 16;
            #pragma unroll
            for (int ni = 0; ni < 8; ++ni) {
                int n = nw * 64 + ni * 8 + 2 * t;
                __half2 v0 = __floats2half2_rn(fmaxf(acc[mi][ni][0], 0.f), fmaxf(acc[mi][ni][1], 0.f));
                __half2 v1 = __floats2half2_rn(fmaxf(acc[mi][ni][2], 0.f), fmaxf(acc[mi][ni][3], 0.f));
                *(uint32_t*)(Hs + (r + g) * HS_STRIDE_H + n)     = *(uint32_t*)&v0;
                *(uint32_t*)(Hs + (r + 8 + g) * HS_STRIDE_H + n) = *(uint32_t*)&v1;
            }
        }
    }
    __syncthreads();

    // ============ stage 2: H[128,256] @ W2^T -> [128,128]; warp tile 32x32 ============
    float acc2[2][4][4];
    {
        const int n0 = nw * 32;
        #pragma unroll
        for (int mi = 0; mi < 2; ++mi)
            #pragma unroll
            for (int ni = 0; ni < 4; ++ni) {
                float bv0 = b2s[n0 + ni * 8 + 2 * t];
                float bv1 = b2s[n0 + ni * 8 + 2 * t + 1];
                acc2[mi][ni][0] = bv0; acc2[mi][ni][1] = bv1;
                acc2[mi][ni][2] = bv0; acc2[mi][ni][3] = bv1;
            }
    }

    // stage2 ldmatrix lane bases
    const uint32_t a2_lane = (uint32_t)(mw * 32 + al_row) * 528 + al_kb;   // Hs stride 264h=528B
    const uint32_t b2_lane = (uint32_t)(nw * 32 + b_row) * 144 + b_kb;

    cpB2(0, hsm + HBS2_0);
    CP_COMMIT();
    CP_WAIT0();
    __syncthreads();

    #pragma unroll 1
    for (int c = 0; c < 4; ++c) {
        if (c < 3) {
            cpB2(c + 1, hsm + ((c + 1) & 1 ? HBS2_1 : HBS2_0));
            CP_COMMIT();
        }
        const uint32_t Ab = smb + a2_lane + (uint32_t)c * 128;   // c*64 halves = 128B
        const uint32_t Bb = smb + ((c & 1) ? HBS2_1 : HBS2_0) * 2 + b2_lane;
        #pragma unroll
        for (int kk = 0; kk < 4; ++kk) {
            const uint32_t kb = (uint32_t)kk * 32;
            uint32_t af[2][4], bf[2][4];
            ldm_x4(af[0], Ab + kb);
            ldm_x4(af[1], Ab + 16 * 528 + kb);
            #pragma unroll
            for (int np = 0; np < 2; ++np)
                ldm_x4(bf[np], Bb + (uint32_t)np * (16 * 144) + kb);
            #pragma unroll
            for (int mi = 0; mi < 2; ++mi)
                #pragma unroll
                for (int np = 0; np < 2; ++np) {
                    mma16(acc2[mi][2 * np],     af[mi], &bf[np][0]);
                    mma16(acc2[mi][2 * np + 1], af[mi], &bf[np][2]);
                }
        }
        if (c < 3) CP_WAIT0();
        __syncthreads();
    }

    // ============ frags -> Hs2 fp32 (aliases Hs; stage2 reads done) ============
    {
        float* Hs2 = sm + OFF_HS2;
        #pragma unroll
        for (int mi = 0; mi < 2; ++mi) {
            int r = mw * 32 + mi * 16;
            #pragma unroll
            for (int ni = 0; ni < 4; ++ni) {
                int n = nw * 32 + ni * 8 + 2 * t;
                Hs2[(r + g) * HS2_STRIDE + n]     = acc2[mi][ni][0];
                Hs2[(r + g) * HS2_STRIDE + n + 1] = acc2[mi][ni][1];
                Hs2[(r + 8 + g) * HS2_STRIDE + n]     = acc2[mi][ni][2];
                Hs2[(r + 8 + g) * HS2_STRIDE + n + 1] = acc2[mi][ni][3];
            }
        }
    }
    __syncthreads();

    // ============ epilogue: contiguous v4 stores + fused segment-sum ============
    {
        const float* Hs2 = sm + OFF_HS2;
        int r = tid >> 2;
        int q = tid & 3;
        int m = m0 + r;
        if (m < M_total) {
            float* op = out + (size_t)m * D + q * 32;
            const float* hp = Hs2 + r * HS2_STRIDE + q * 32;
            if (mode == 0) {
                float* ps = g_sent_agg + (size_t)sid[r] * D + q * 32;
                float* pr = g_recv_agg + (size_t)rid[r] * D + q * 32;
                #pragma unroll
                for (int i = 0; i < 8; ++i) {
                    float4 v = *(const float4*)(hp + 4 * i);
                    *(float4*)(op + 4 * i) = v;
                    red_add_v4(ps + 4 * i, v);
                    red_add_v4(pr + 4 * i, v);
                }
            } else {
                #pragma unroll
                for (int i = 0; i < 8; ++i)
                    *(float4*)(op + 4 * i) = *(const float4*)(hp + 4 * i);
            }
        }
    }
}

// -------------------- launch --------------------
extern "C" void kernel_launch(void* const* d_in, const int* in_sizes, int n_in,
                              void* d_out, int out_size)
{
    const float* node_feat = (const float*)d_in[0];
    const float* edge_feat = (const float*)d_in[1];
    const int*   senders   = (const int*)  d_in[2];
    const int*   receivers = (const int*)  d_in[3];
    const float* eW1 = (const float*)d_in[4];
    const float* eb1 = (const float*)d_in[5];
    const float* eW2 = (const float*)d_in[6];
    const float* eb2 = (const float*)d_in[7];
    const float* nW1 = (const float*)d_in[8];
    const float* nb1 = (const float*)d_in[9];
    const float* nW2 = (const float*)d_in[10];
    const float* nb2 = (const float*)d_in[11];

    const int N = in_sizes[0] / D;
    const int E = in_sizes[2];

    float* new_nodes = (float*)d_out;
    float* new_edges = new_nodes + (size_t)N * D;

    cudaFuncSetAttribute(gn_mlp_kernel,
                         cudaFuncAttributeMaxDynamicSharedMemorySize, SMEM_BYTES);

    void *pa, *pb;
    cudaGetSymbolAddress(&pa, g_sent_agg);
    cudaGetSymbolAddress(&pb, g_recv_agg);
    cudaMemsetAsync(pa, 0, sizeof(float) * MAXN * D);
    cudaMemsetAsync(pb, 0, sizeof(float) * MAXN * D);

    prep_weights<<<192, 512>>>(eW1, eW2, nW1, nW2);

    int eblocks = (E + TM - 1) / TM;
    gn_mlp_kernel<<<eblocks, NTHR, SMEM_BYTES>>>(
        node_feat, edge_feat, senders, receivers,
        eb1, eb2, new_edges, E, 0);

    int nblocks = (N + TM - 1) / TM;
    gn_mlp_kernel<<<nblocks, NTHR, SMEM_BYTES>>>(
        node_feat, nullptr, nullptr, nullptr,
        nb1, nb2, new_nodes, N, 1);
}

// round 11
// speedup vs baseline: 1.7990x; 1.0567x over previous
#include <cuda_runtime.h>
#include <cuda_fp16.h>
#include <cstdint>

#define D     128
#define HID   256
#define KIN   384
#define TM    64
#define NTHR  256
#define MAXN  50000

// -------------------- device scratch --------------------
__device__ float g_sent_agg[MAXN * D];
__device__ float g_recv_agg[MAXN * D];
__device__ __align__(16) __half g_ew1t[HID * KIN];   // W1^T [256,384] fp16
__device__ __align__(16) __half g_ew2t[D * HID];     // W2^T [128,256]
__device__ __align__(16) __half g_nw1t[HID * KIN];
__device__ __align__(16) __half g_nw2t[D * HID];

__device__ __forceinline__ void mma16(float d[4], const uint32_t a[4], const uint32_t b[2]) {
    asm volatile("mma.sync.aligned.m16n8k16.row.col.f32.f16.f16.f32 "
                 "{%0,%1,%2,%3}, {%4,%5,%6,%7}, {%8,%9}, {%0,%1,%2,%3};"
                 : "+f"(d[0]), "+f"(d[1]), "+f"(d[2]), "+f"(d[3])
                 : "r"(a[0]), "r"(a[1]), "r"(a[2]), "r"(a[3]),
                   "r"(b[0]), "r"(b[1]));
}

__device__ __forceinline__ void ldm_x4(uint32_t r[4], uint32_t saddr) {
    asm volatile("ldmatrix.sync.aligned.m8n8.x4.shared.b16 {%0,%1,%2,%3}, [%4];"
                 : "=r"(r[0]), "=r"(r[1]), "=r"(r[2]), "=r"(r[3]) : "r"(saddr));
}

__device__ __forceinline__ void red_add_v4(float* p, float4 v) {
    asm volatile("red.global.add.v4.f32 [%0], {%1,%2,%3,%4};"
                 :: "l"(p), "f"(v.x), "f"(v.y), "f"(v.z), "f"(v.w) : "memory");
}

__device__ __forceinline__ void cp16(__half* smem_dst, const __half* gsrc) {
    uint32_t s = (uint32_t)__cvta_generic_to_shared(smem_dst);
    asm volatile("cp.async.cg.shared.global [%0], [%1], 16;" :: "r"(s), "l"(gsrc));
}
#define CP_COMMIT() asm volatile("cp.async.commit_group;" ::: "memory")
#define CP_WAIT0()  asm volatile("cp.async.wait_group 0;"  ::: "memory")

// -------------------- weight prep: transpose + fp16 --------------------
__global__ void prep_weights(const float* __restrict__ eW1, const float* __restrict__ eW2,
                             const float* __restrict__ nW1, const float* __restrict__ nW2)
{
    int idx0 = blockIdx.x * blockDim.x + threadIdx.x;
    int stride = gridDim.x * blockDim.x;
    for (int i = idx0; i < HID * KIN; i += stride) {
        int n = i / KIN, k = i - n * KIN;
        g_ew1t[i] = __float2half_rn(eW1[k * HID + n]);
        g_nw1t[i] = __float2half_rn(nW1[k * HID + n]);
    }
    for (int i = idx0; i < D * HID; i += stride) {
        int n = i / HID, k = i - n * HID;
        g_ew2t[i] = __float2half_rn(eW2[k * D + n]);
        g_nw2t[i] = __float2half_rn(nW2[k * D + n]);
    }
}

// -------------------- smem layout (TM=64, 2 CTAs/SM) --------------------
// half offsets (stride 72 halves = 144B rows):
//   As0 [64][72] @0, As1 @4608, Bs0 [256][72] @9216, Bs1 @27648 (end 46080)
//   Hs  [64][264] @0 (16896 halves; aliases As0/As1/Bs0-head — dead post-stage1)
//   Bs2_0 [128][72] @27648, Bs2_1 @36864 (alias Bs1 — dead post-stage1)
// float offsets:
//   Hs2 [64][132] @0 (8448 floats = Hs bytes; dead-Hs after stage2 final sync)
//   b1s @23040, b2s @23296, sid @23424, rid @23488 (end 23552 floats)
#define HAS0   0
#define HAS1   4608
#define HBS0   9216
#define HBS1   27648
#define HHS    0
#define HS_STRIDE_H 264
#define HBS2_0 27648
#define HBS2_1 36864
#define OFF_HS2   0
#define HS2_STRIDE 132
#define OFF_B1S   23040
#define OFF_B2S   23296
#define OFF_SID   23424
#define OFF_RID   23488
#define SMEM_BYTES 94208

// -------------------- fused MLP kernel --------------------
// mode 0: edge MLP (+ fused segment-sum), mode 1: node MLP
__global__ __launch_bounds__(NTHR, 2)
void gn_mlp_kernel(const float* __restrict__ in0,
                   const float* __restrict__ edge_feat,
                   const int*   __restrict__ senders,
                   const int*   __restrict__ receivers,
                   const float* __restrict__ b1,
                   const float* __restrict__ b2,
                   float* __restrict__ out,
                   int M_total, int mode)
{
    extern __shared__ float sm[];
    __half* hsm = (__half*)sm;
    float* b1s = sm + OFF_B1S;
    float* b2s = sm + OFF_B2S;
    int*   sid = (int*)(sm + OFF_SID);
    int*   rid = (int*)(sm + OFF_RID);

    const int tid  = threadIdx.x;
    const int lane = tid & 31;
    const int w    = tid >> 5;         // 0..7
    const int g    = lane >> 2;
    const int t    = lane & 3;
    const int mw   = w & 1;            // 2 M tiles (32 rows each)
    const int nw   = w >> 1;           // 4 N tiles
    const int m0   = blockIdx.x * TM;

    const __half* __restrict__ w1t = (mode == 0) ? g_ew1t : g_nw1t;
    const __half* __restrict__ w2t = (mode == 0) ? g_ew2t : g_nw2t;

    const uint32_t smb = (uint32_t)__cvta_generic_to_shared(hsm);

    // ldmatrix lane geometry
    const int al_row = lane & 15;
    const uint32_t al_kb = (uint32_t)(lane >> 4) * 16;
    const int bl_j = lane >> 3, bl_i = lane & 7;
    const int b_row = ((bl_j >> 1) << 3) + bl_i;
    const uint32_t b_kb = (uint32_t)(bl_j & 1) * 16;

    for (int i = tid; i < HID; i += NTHR) b1s[i] = b1[i];
    for (int i = tid; i < D;   i += NTHR) b2s[i] = b2[i];
    if (mode == 0) {
        if (tid < TM) {
            int e = m0 + tid;
            sid[tid] = (e < M_total) ? senders[e]   : 0;
            rid[tid] = (e < M_total) ? receivers[e] : 0;
        }
    }
    __syncthreads();

    // ---- A gather: 4 float4 segs/thread/chunk; rows arow+16i ----
    const int arow = tid >> 4;          // 0..15
    const int asc  = tid & 15;          // float4 index within 64 cols
    float4 a_pre[4];
    auto ldA = [&](int c) {
        const int csel = c >> 1;
        const int co = (c & 1) * 64 + asc * 4;
        #pragma unroll
        for (int i = 0; i < 4; ++i) {
            int r = arow + 16 * i;
            int m = m0 + r;
            bool ok = (m < M_total);
            const float* bp;
            if (mode == 0) {
                int s = (csel == 0) ? m : (csel == 1 ? sid[r] : rid[r]);
                bp = ((csel == 0) ? edge_feat : in0) + (size_t)s * D;
            } else {
                bp = ((csel == 0) ? in0 : (csel == 1 ? g_sent_agg : g_recv_agg)) + (size_t)m * D;
            }
            a_pre[i] = ok ? *(const float4*)(bp + co) : make_float4(0.f, 0.f, 0.f, 0.f);
        }
    };
    auto stA = [&](__half* dst) {
        #pragma unroll
        for (int i = 0; i < 4; ++i) {
            __half2 lo = __floats2half2_rn(a_pre[i].x, a_pre[i].y);
            __half2 hi = __floats2half2_rn(a_pre[i].z, a_pre[i].w);
            uint2 tv;
            tv.x = *(uint32_t*)&lo; tv.y = *(uint32_t*)&hi;
            *(uint2*)(dst + (arow + 16 * i) * 72 + asc * 4) = tv;
        }
    };
    auto cpB1 = [&](int c, __half* dst) {       // 256 rows x 8 segs = 2048 cp16
        #pragma unroll
        for (int it = 0; it < 8; ++it) {
            int seg = tid + NTHR * it;
            int row = seg >> 3, sc = seg & 7;
            cp16(dst + row * 72 + sc * 8, w1t + (size_t)row * KIN + c * 64 + sc * 8);
        }
    };
    auto cpB2 = [&](int c, __half* dst) {       // 128 rows x 8 segs = 1024 cp16
        #pragma unroll
        for (int it = 0; it < 4; ++it) {
            int seg = tid + NTHR * it;
            int row = seg >> 3, sc = seg & 7;
            cp16(dst + row * 72 + sc * 8, w2t + (size_t)row * HID + c * 64 + sc * 8);
        }
    };

    // ============ stage 1: [64,384] @ W1^T -> [64,256]; warp tile 32x64 ============
    float acc[2][8][4];
    {
        const int n0 = nw * 64;
        #pragma unroll
        for (int mi = 0; mi < 2; ++mi)
            #pragma unroll
            for (int ni = 0; ni < 8; ++ni) {
                float bv0 = b1s[n0 + ni * 8 + 2 * t];
                float bv1 = b1s[n0 + ni * 8 + 2 * t + 1];
                acc[mi][ni][0] = bv0; acc[mi][ni][1] = bv1;
                acc[mi][ni][2] = bv0; acc[mi][ni][3] = bv1;
            }
    }

    const uint32_t a1_lane = (uint32_t)(mw * 32 + al_row) * 144 + al_kb;
    const uint32_t b1_lane = (uint32_t)(nw * 64 + b_row) * 144 + b_kb;

    ldA(0);
    cpB1(0, hsm + HBS0);
    CP_COMMIT();
    stA(hsm + HAS0);
    CP_WAIT0();
    __syncthreads();

    #pragma unroll 1
    for (int c = 0; c < 6; ++c) {
        if (c < 5) {
            ldA(c + 1);
            cpB1(c + 1, hsm + ((c + 1) & 1 ? HBS1 : HBS0));
            CP_COMMIT();
        }
        const uint32_t Ab = smb + ((c & 1) ? HAS1 : HAS0) * 2 + a1_lane;
        const uint32_t Bb = smb + ((c & 1) ? HBS1 : HBS0) * 2 + b1_lane;
        #pragma unroll
        for (int kk = 0; kk < 4; ++kk) {
            const uint32_t kb = (uint32_t)kk * 32;
            uint32_t af[2][4], bf[4][4];
            ldm_x4(af[0], Ab + kb);
            ldm_x4(af[1], Ab + 16 * 144 + kb);
            #pragma unroll
            for (int np = 0; np < 4; ++np)
                ldm_x4(bf[np], Bb + (uint32_t)np * (16 * 144) + kb);
            #pragma unroll
            for (int mi = 0; mi < 2; ++mi)
                #pragma unroll
                for (int np = 0; np < 4; ++np) {
                    mma16(acc[mi][2 * np],     af[mi], &bf[np][0]);
                    mma16(acc[mi][2 * np + 1], af[mi], &bf[np][2]);
                }
        }
        if (c < 5) {
            stA(hsm + ((c + 1) & 1 ? HAS1 : HAS0));
            CP_WAIT0();
        }
        __syncthreads();
    }

    // ============ hidden: relu -> fp16, store to Hs (aliases dead stage1 bufs) =====
    {
        __half* Hs = hsm + HHS;
        #pragma unroll
        for (int mi = 0; mi < 2; ++mi) {
            int r = mw * 32 + mi * 16;
            #pragma unroll
            for (int ni = 0; ni < 8; ++ni) {
                int n = nw * 64 + ni * 8 + 2 * t;
                __half2 v0 = __floats2half2_rn(fmaxf(acc[mi][ni][0], 0.f), fmaxf(acc[mi][ni][1], 0.f));
                __half2 v1 = __floats2half2_rn(fmaxf(acc[mi][ni][2], 0.f), fmaxf(acc[mi][ni][3], 0.f));
                *(uint32_t*)(Hs + (r + g) * HS_STRIDE_H + n)     = *(uint32_t*)&v0;
                *(uint32_t*)(Hs + (r + 8 + g) * HS_STRIDE_H + n) = *(uint32_t*)&v1;
            }
        }
    }
    __syncthreads();

    // ============ stage 2: H[64,256] @ W2^T -> [64,128]; warp tile 32x32 ============
    float acc2[2][4][4];
    {
        const int n0 = nw * 32;
        #pragma unroll
        for (int mi = 0; mi < 2; ++mi)
            #pragma unroll
            for (int ni = 0; ni < 4; ++ni) {
                float bv0 = b2s[n0 + ni * 8 + 2 * t];
                float bv1 = b2s[n0 + ni * 8 + 2 * t + 1];
                acc2[mi][ni][0] = bv0; acc2[mi][ni][1] = bv1;
                acc2[mi][ni][2] = bv0; acc2[mi][ni][3] = bv1;
            }
    }

    const uint32_t a2_lane = (uint32_t)(mw * 32 + al_row) * 528 + al_kb;   // Hs 264h=528B
    const uint32_t b2_lane = (uint32_t)(nw * 32 + b_row) * 144 + b_kb;

    cpB2(0, hsm + HBS2_0);
    CP_COMMIT();
    CP_WAIT0();
    __syncthreads();

    #pragma unroll 1
    for (int c = 0; c < 4; ++c) {
        if (c < 3) {
            cpB2(c + 1, hsm + ((c + 1) & 1 ? HBS2_1 : HBS2_0));
            CP_COMMIT();
        }
        const uint32_t Ab = smb + a2_lane + (uint32_t)c * 128;   // c*64 halves = 128B
        const uint32_t Bb = smb + ((c & 1) ? HBS2_1 : HBS2_0) * 2 + b2_lane;
        #pragma unroll
        for (int kk = 0; kk < 4; ++kk) {
            const uint32_t kb = (uint32_t)kk * 32;
            uint32_t af[2][4], bf[2][4];
            ldm_x4(af[0], Ab + kb);
            ldm_x4(af[1], Ab + 16 * 528 + kb);
            #pragma unroll
            for (int np = 0; np < 2; ++np)
                ldm_x4(bf[np], Bb + (uint32_t)np * (16 * 144) + kb);
            #pragma unroll
            for (int mi = 0; mi < 2; ++mi)
                #pragma unroll
                for (int np = 0; np < 2; ++np) {
                    mma16(acc2[mi][2 * np],     af[mi], &bf[np][0]);
                    mma16(acc2[mi][2 * np + 1], af[mi], &bf[np][2]);
                }
        }
        if (c < 3) CP_WAIT0();
        __syncthreads();
    }

    // ============ frags -> Hs2 fp32 (aliases Hs; stage2 reads done) ============
    {
        float* Hs2 = sm + OFF_HS2;
        #pragma unroll
        for (int mi = 0; mi < 2; ++mi) {
            int r = mw * 32 + mi * 16;
            #pragma unroll
            for (int ni = 0; ni < 4; ++ni) {
                int n = nw * 32 + ni * 8 + 2 * t;
                Hs2[(r + g) * HS2_STRIDE + n]     = acc2[mi][ni][0];
                Hs2[(r + g) * HS2_STRIDE + n + 1] = acc2[mi][ni][1];
                Hs2[(r + 8 + g) * HS2_STRIDE + n]     = acc2[mi][ni][2];
                Hs2[(r + 8 + g) * HS2_STRIDE + n + 1] = acc2[mi][ni][3];
            }
        }
    }
    __syncthreads();

    // ============ epilogue: contiguous v4 stores + fused segment-sum ============
    {
        const float* Hs2 = sm + OFF_HS2;
        int r = tid >> 2;          // 0..63
        int q = tid & 3;
        int m = m0 + r;
        if (m < M_total) {
            float* op = out + (size_t)m * D + q * 32;
            const float* hp = Hs2 + r * HS2_STRIDE + q * 32;
            if (mode == 0) {
                float* ps = g_sent_agg + (size_t)sid[r] * D + q * 32;
                float* pr = g_recv_agg + (size_t)rid[r] * D + q * 32;
                #pragma unroll
                for (int i = 0; i < 8; ++i) {
                    float4 v = *(const float4*)(hp + 4 * i);
                    *(float4*)(op + 4 * i) = v;
                    red_add_v4(ps + 4 * i, v);
                    red_add_v4(pr + 4 * i, v);
                }
            } else {
                #pragma unroll
                for (int i = 0; i < 8; ++i)
                    *(float4*)(op + 4 * i) = *(const float4*)(hp + 4 * i);
            }
        }
    }
}

// -------------------- launch --------------------
extern "C" void kernel_launch(void* const* d_in, const int* in_sizes, int n_in,
                              void* d_out, int out_size)
{
    const float* node_feat = (const float*)d_in[0];
    const float* edge_feat = (const float*)d_in[1];
    const int*   senders   = (const int*)  d_in[2];
    const int*   receivers = (const int*)  d_in[3];
    const float* eW1 = (const float*)d_in[4];
    const float* eb1 = (const float*)d_in[5];
    const float* eW2 = (const float*)d_in[6];
    const float* eb2 = (const float*)d_in[7];
    const float* nW1 = (const float*)d_in[8];
    const float* nb1 = (const float*)d_in[9];
    const float* nW2 = (const float*)d_in[10];
    const float* nb2 = (const float*)d_in[11];

    const int N = in_sizes[0] / D;
    const int E = in_sizes[2];

    float* new_nodes = (float*)d_out;
    float* new_edges = new_nodes + (size_t)N * D;

    cudaFuncSetAttribute(gn_mlp_kernel,
                         cudaFuncAttributeMaxDynamicSharedMemorySize, SMEM_BYTES);

    void *pa, *pb;
    cudaGetSymbolAddress(&pa, g_sent_agg);
    cudaGetSymbolAddress(&pb, g_recv_agg);
    cudaMemsetAsync(pa, 0, sizeof(float) * MAXN * D);
    cudaMemsetAsync(pb, 0, sizeof(float) * MAXN * D);

    prep_weights<<<192, 512>>>(eW1, eW2, nW1, nW2);

    int eblocks = (E + TM - 1) / TM;
    gn_mlp_kernel<<<eblocks, NTHR, SMEM_BYTES>>>(
        node_feat, edge_feat, senders, receivers,
        eb1, eb2, new_edges, E, 0);

    int nblocks = (N + TM - 1) / TM;
    gn_mlp_kernel<<<nblocks, NTHR, SMEM_BYTES>>>(
        node_feat, nullptr, nullptr, nullptr,
        nb1, nb2, new_nodes, N, 1);
}